// round 3
// baseline (speedup 1.0000x reference)
#include <cuda_runtime.h>
#include <cstdint>

// Problem constants
#define CELLS (1 << 21)           // 128^3 coarse cells, 21-bit packed key
#define SCAN_CHUNK 2048           // elements per scan block (256 thr x 8)
#define SCAN_BLOCKS (CELLS / SCAN_CHUNK)  // 1024
#define MAXN 524288               // >= 500000

// Scratch (static device globals; allocation-free)
__device__ __align__(16) unsigned int g_mark[CELLS];
__device__ __align__(16) unsigned int g_rank[CELLS];
__device__ unsigned int g_bsum[SCAN_BLOCKS];
__device__ unsigned int g_numu;
__device__ int g_winner[MAXN * 8];

// ---------------------------------------------------------------------------
// Pass 1: mark occupied coarse cells
__global__ void markK(const int* __restrict__ coords, int n) {
    int i = blockIdx.x * blockDim.x + threadIdx.x;
    if (i >= n) return;
    int cx = coords[3 * i + 0] >> 1;
    int cy = coords[3 * i + 1] >> 1;
    int cz = coords[3 * i + 2] >> 1;
    unsigned key = ((unsigned)cx << 14) | ((unsigned)cy << 7) | (unsigned)cz;
    g_mark[key] = 1u;
}

// ---------------------------------------------------------------------------
// Scan stage A: per-block sums of 2048 marks
__global__ void scanA() {
    __shared__ unsigned int s[256];
    int t = threadIdx.x;
    int base = blockIdx.x * SCAN_CHUNK + t * 8;
    const uint4* p = (const uint4*)&g_mark[base];
    uint4 a = p[0], b = p[1];
    unsigned sum = a.x + a.y + a.z + a.w + b.x + b.y + b.z + b.w;
    s[t] = sum;
    __syncthreads();
    for (int o = 128; o > 0; o >>= 1) {
        if (t < o) s[t] += s[t + o];
        __syncthreads();
    }
    if (t == 0) g_bsum[blockIdx.x] = s[0];
}

// Scan stage B: exclusive scan of the 1024 block sums (single block)
__global__ void scanB() {
    __shared__ unsigned int s[SCAN_BLOCKS];
    int t = threadIdx.x;
    unsigned v = g_bsum[t];
    s[t] = v;
    __syncthreads();
    for (int o = 1; o < SCAN_BLOCKS; o <<= 1) {
        unsigned add = (t >= o) ? s[t - o] : 0u;
        __syncthreads();
        s[t] += add;
        __syncthreads();
    }
    g_bsum[t] = s[t] - v;                 // exclusive
    if (t == SCAN_BLOCKS - 1) g_numu = s[SCAN_BLOCKS - 1];
}

// Scan stage C: final per-element exclusive prefix -> g_rank
__global__ void scanC() {
    __shared__ unsigned int s[256];
    int t = threadIdx.x;
    int base = blockIdx.x * SCAN_CHUNK + t * 8;
    const uint4* p = (const uint4*)&g_mark[base];
    uint4 a = p[0], b = p[1];
    unsigned e[8] = {a.x, a.y, a.z, a.w, b.x, b.y, b.z, b.w};
    unsigned sum = 0;
#pragma unroll
    for (int i = 0; i < 8; i++) sum += e[i];
    s[t] = sum;
    __syncthreads();
    for (int o = 1; o < 256; o <<= 1) {
        unsigned add = (t >= o) ? s[t - o] : 0u;
        __syncthreads();
        s[t] += add;
        __syncthreads();
    }
    unsigned run = s[t] - sum + g_bsum[blockIdx.x];
#pragma unroll
    for (int i = 0; i < 8; i++) {
        g_rank[base + i] = run;
        run += e[i];
    }
}

// ---------------------------------------------------------------------------
// Fill the coords region of the output with -1 (padding rows)
__global__ void fillCoordsK(float* __restrict__ outc, int n3) {
    int i = blockIdx.x * blockDim.x + threadIdx.x;
    if (i < n3) outc[i] = -1.0f;
}

// Write sorted-unique coarse coords (row = rank[key])
__global__ void writeUniqueK(float* __restrict__ outc) {
    int c = blockIdx.x * blockDim.x + threadIdx.x;
    if (c >= CELLS) return;
    if (g_mark[c]) {
        unsigned row = g_rank[c];
        outc[row * 3 + 0] = (float)((c >> 14) & 127);
        outc[row * 3 + 1] = (float)((c >> 7) & 127);
        outc[row * 3 + 2] = (float)(c & 127);
    }
}

// ---------------------------------------------------------------------------
// Winner resolution: last point index wins per (row, offset) slot
__global__ void winnerK(const int* __restrict__ coords, int n) {
    int i = blockIdx.x * blockDim.x + threadIdx.x;
    if (i >= n) return;
    int x = coords[3 * i + 0];
    int y = coords[3 * i + 1];
    int z = coords[3 * i + 2];
    unsigned key = ((unsigned)(x >> 1) << 14) | ((unsigned)(y >> 1) << 7) | (unsigned)(z >> 1);
    unsigned row = g_rank[key];
    int off = (x & 1) * 4 + (y & 1) * 2 + (z & 1);
    atomicMax(&g_winner[row * 8 + off], i);
}

// Scatter features: 4 threads per point, one float4 each
__global__ void scatterK(const float* __restrict__ feats,
                         const int* __restrict__ coords,
                         float* __restrict__ agg, int n) {
    int j = blockIdx.x * blockDim.x + threadIdx.x;
    int i = j >> 2;
    int q = j & 3;
    if (i >= n) return;
    int x = coords[3 * i + 0];
    int y = coords[3 * i + 1];
    int z = coords[3 * i + 2];
    unsigned key = ((unsigned)(x >> 1) << 14) | ((unsigned)(y >> 1) << 7) | (unsigned)(z >> 1);
    unsigned row = g_rank[key];
    int off = (x & 1) * 4 + (y & 1) * 2 + (z & 1);
    if (g_winner[row * 8 + off] != i) return;  // deterministic last-wins
    float4 v = ((const float4*)feats)[i * 4 + q];
    ((float4*)agg)[(row * 128 + off * 16) / 4 + q] = v;
}

// ---------------------------------------------------------------------------
extern "C" void kernel_launch(void* const* d_in, const int* in_sizes, int n_in,
                              void* d_out, int out_size) {
    // feats is the larger buffer (N*16 vs N*3)
    const float* feats;
    const int* coords;
    int n;
    if (in_sizes[0] >= in_sizes[1]) {
        feats = (const float*)d_in[0];
        coords = (const int*)d_in[1];
        n = in_sizes[1] / 3;
    } else {
        feats = (const float*)d_in[1];
        coords = (const int*)d_in[0];
        n = in_sizes[0] / 3;
    }

    float* outc = (float*)d_out;            // [N,3] unique coords (as float)
    float* agg = outc + (size_t)n * 3;      // [N,128] aggregated features

    void* p_mark; cudaGetSymbolAddress(&p_mark, g_mark);
    void* p_winner; cudaGetSymbolAddress(&p_winner, g_winner);

    // Clear scratch + zero agg output
    cudaMemsetAsync(p_mark, 0, sizeof(unsigned int) * CELLS);
    cudaMemsetAsync(p_winner, 0xFF, sizeof(int) * 8 * (size_t)n);
    cudaMemsetAsync(agg, 0, sizeof(float) * 128 * (size_t)n);

    int tb = 256;
    markK<<<(n + tb - 1) / tb, tb>>>(coords, n);
    scanA<<<SCAN_BLOCKS, 256>>>();
    scanB<<<1, SCAN_BLOCKS>>>();
    scanC<<<SCAN_BLOCKS, 256>>>();
    fillCoordsK<<<(n * 3 + tb - 1) / tb, tb>>>(outc, n * 3);
    writeUniqueK<<<CELLS / tb, tb>>>(outc);
    winnerK<<<(n + tb - 1) / tb, tb>>>(coords, n);
    scatterK<<<(n * 4 + tb - 1) / tb, tb>>>(feats, coords, agg, n);
}